// round 13
// baseline (speedup 1.0000x reference)
#include <cuda_runtime.h>
#include <cuda_fp16.h>

#define I_DIM   128
#define O_DIM   128
#define G_NUM   128
#define G1      129
#define B_DIM   8192
#define C_CHUNKS 4
#define ICHUNK  (I_DIM / C_CHUNKS)   /* 32 */
#define BT      256                  /* batch columns per block */
#define NBT     (B_DIM / BT)         /* 32 */
#define THREADS 512
#define NWARP   (THREADS / 32)       /* 16 */
#define BPW     (BT / NWARP)         /* 16 batch columns per warp */
#define ROW_U2  (O_DIM / 4)          /* 32 uint2 per 256B fp16 row */
#define TI      16                   /* i per transpose tile */

#define G_SPLIT 79                   /* gi < 79 -> smem path (rows 0..79 staged) */
#define SROWS   80                   /* staged rows per slice */
#define SLICE_SB (SROWS * 256)       /* 20480 B staged per slice */
#define WIN_SB   (4 * SLICE_SB)      /* 81920 B per window */
#define SLICE_GB (G1 * 256)          /* 33024 B full slice in global */

// dynamic smem layout
#define OFF_TAB  0                           /* 2 windows: 163840 */
#define OFF_GD   (2 * WIN_SB)                /* 32 KB descriptors */
#define OFF_SB   (OFF_GD + ICHUNK * BT * 4)  /* 196608+ */
#define OFF_SIL  (OFF_SB + 132 * 4)
#define SMEM_MAIN (OFF_SIL + 128 * 4 + 16)   /* ~197.7 KB */

// Static device scratch (allocation-free per harness rules)
__device__ __align__(256) __half g_P2h[(size_t)I_DIM * G1 * O_DIM];   // [i][g][o] 4.2MB
__device__ __align__(16) __half g_partialH[C_CHUNKS][B_DIM][O_DIM];   // [c][b][o] fp16 8MB

// ---------------------------------------------------------------------------
// Kernel 1 (round-10, stable): transpose+quantize P[g][o][i] -> P2h[i][g][o].
// ---------------------------------------------------------------------------
__global__ __launch_bounds__(256, 8)
void transpose_kernel(const float* __restrict__ P) {
    __shared__ float tile[2][O_DIM][17];
    const int g0 = blockIdx.y * 2;
    const int i0 = blockIdx.x * TI;
    const int t = threadIdx.x;
    const int w = t >> 5, lane = t & 31;
    const int gg = w >> 2;
    const int w2 = w & 3;
    const int oq = lane >> 2;
    const int f4 = lane & 3;
    const int g = g0 + gg;

    if (g <= G_NUM) {
        const float4* src = (const float4*)(P + (size_t)g * O_DIM * I_DIM + i0);
        float4 v[4];
#pragma unroll
        for (int r = 0; r < 4; r++) {
            int o = w2 * 32 + r * 8 + oq;
            v[r] = src[(size_t)o * (I_DIM / 4) + f4];
        }
#pragma unroll
        for (int r = 0; r < 4; r++) {
            int o = w2 * 32 + r * 8 + oq;
            tile[gg][o][f4 * 4 + 0] = v[r].x;
            tile[gg][o][f4 * 4 + 1] = v[r].y;
            tile[gg][o][f4 * 4 + 2] = v[r].z;
            tile[gg][o][f4 * 4 + 3] = v[r].w;
        }
    }
    __syncthreads();

    const int op  = t & 63;
    const int il  = (t >> 6) & 1;
    const int gg2 = t >> 7;
    const int gs  = g0 + gg2;
    if (gs <= G_NUM) {
        __half2* dst = (__half2*)g_P2h;
#pragma unroll
        for (int r = 0; r < 8; r++) {
            int i = il + 2 * r;
            dst[((size_t)(i0 + i) * G1 + gs) * (O_DIM / 2) + op] =
                __floats2half2_rn(tile[gg2][2 * op][i], tile[gg2][2 * op + 1][i]);
        }
    }
}

// ---------------------------------------------------------------------------
// Kernel 2: dual-pipe gather. Rows g<80 of each window's slices are staged
// into double-buffered smem (preloaded during the PREVIOUS window, sealed by
// the existing window barrier); gathers branch warp-uniformly: gi<79 -> LDS
// (crossbar pipe), gi>=79 -> LDG/L1 pipe. Two independent 128B/cyc pipes.
// ---------------------------------------------------------------------------
__global__ __launch_bounds__(THREADS, 1)
void main_kernel(const float* __restrict__ x,
                 const float* __restrict__ borders,
                 const float* __restrict__ invl) {
    extern __shared__ __align__(16) char smem[];
    char*     s_tab = smem + OFF_TAB;
    unsigned* s_gd  = (unsigned*)(smem + OFF_GD);   // [ICHUNK][BT]
    float*    s_b   = (float*)(smem + OFF_SB);
    float*    s_il  = (float*)(smem + OFF_SIL);

    const int t     = threadIdx.x;
    const int btile = blockIdx.x;    // 0..31
    const int chunk = blockIdx.y;    // 0..3
    const int b0    = btile * BT;
    const int i0    = chunk * ICHUNK;

    const int w    = t >> 5;
    const int lane = t & 31;
    const int su_p = w & 3;          // preload: slice within window
    const int seg  = w >> 2;         // preload: quarter of staged bytes

    if (t < G1)    s_b[t]  = borders[t];
    if (t < G_NUM) s_il[t] = invl[t];

    // Preload window 0 (slices i0..i0+3, rows 0..79) into buffer 0.
    {
        const uint4* src = (const uint4*)((const char*)g_P2h +
                            (size_t)(i0 + su_p) * SLICE_GB + seg * (SLICE_SB / 4));
        uint4* dst = (uint4*)(s_tab + su_p * SLICE_SB + seg * (SLICE_SB / 4));
#pragma unroll
        for (int r = 0; r < SLICE_SB / 4 / 512; r++)   // 10 iters of 512B
            dst[r * 32 + lane] = src[r * 32 + lane];
    }
    __syncthreads();

    // Phase 1: bucket index g + weight d, packed (g | half(d)<<16)
    {
        const int bl    = t & (BT - 1);
        const int ibase = t >> 8;
#pragma unroll
        for (int p = 0; p < ICHUNK / 2; p++) {
            int il = ibase + 2 * p;
            float xv = x[(size_t)(i0 + il) * B_DIM + b0 + bl];
            float e  = __expf(-fabsf(xv));
            float cdf = (xv > 0.f) ? (1.f - 0.5f * e) : (0.5f * e);
            int g = (int)(cdf * (float)G_NUM);
            g = min(max(g, 0), G_NUM - 1);
            float d = (xv - s_b[g]) * s_il[g];
            unsigned db = (unsigned)__half_as_ushort(__float2half_rn(d));
            s_gd[il * BT + bl] = (unsigned)g | (db << 16);
        }
    }
    __syncthreads();

    const int wb = w * BPW;
    const __half2 one2 = __floats2half2_rn(1.f, 1.f);
    const __half2 z2   = __floats2half2_rn(0.f, 0.f);
    const uint2* __restrict__ P2v = (const uint2*)g_P2h;

    float4 accF[BPW];
#pragma unroll
    for (int j = 0; j < BPW; j++) accF[j] = make_float4(0.f, 0.f, 0.f, 0.f);

    for (int W = 0; W < ICHUNK / 4; W++) {
        const int iiB  = W * 4;
        const int bsel = W & 1;
        __half2 a0[BPW], a1[BPW];
#pragma unroll
        for (int j = 0; j < BPW; j++) { a0[j] = z2; a1[j] = z2; }

#pragma unroll
        for (int u = 0; u < 4; u++) {
            const int ii = iiB + u;
            const uint2* gslice = P2v + (size_t)(i0 + ii) * (G1 * ROW_U2);
            const char*  sslice = s_tab + bsel * WIN_SB + u * SLICE_SB;
#pragma unroll
            for (int j = 0; j < BPW; j++) {
                unsigned v  = s_gd[ii * BT + wb + j];   // broadcast LDS
                unsigned gi = v & 0xFFu;
                unsigned dd = __byte_perm(v, v, 0x3232);
                __half2 d2  = *(__half2*)&dd;
                __half2 w2  = __hsub2(one2, d2);
                uint2 A, Bv;
                if (gi < G_SPLIT) {     // warp-uniform branch -> smem pipe
                    const uint2* rowp = (const uint2*)(sslice + gi * 256) + lane;
                    A  = rowp[0];
                    Bv = rowp[ROW_U2];
                } else {                // L1 pipe
                    const uint2* rowp = gslice + gi * ROW_U2 + lane;
                    A  = __ldg(rowp);
                    Bv = __ldg(rowp + ROW_U2);
                }
                a0[j] = __hfma2(w2, *(__half2*)&A.x,  a0[j]);
                a0[j] = __hfma2(d2, *(__half2*)&Bv.x, a0[j]);
                a1[j] = __hfma2(w2, *(__half2*)&A.y,  a1[j]);
                a1[j] = __hfma2(d2, *(__half2*)&Bv.y, a1[j]);
            }
        }

        // Preload next window into the other buffer (sealed by barrier below).
        if (W < ICHUNK / 4 - 1) {
            const uint4* src = (const uint4*)((const char*)g_P2h +
                    (size_t)(i0 + iiB + 4 + su_p) * SLICE_GB + seg * (SLICE_SB / 4));
            uint4* dst = (uint4*)(s_tab + (bsel ^ 1) * WIN_SB +
                                  su_p * SLICE_SB + seg * (SLICE_SB / 4));
#pragma unroll
            for (int r = 0; r < SLICE_SB / 4 / 512; r++)
                dst[r * 32 + lane] = src[r * 32 + lane];
        }

        // flush half2 partials into fp32 accumulators every 4 slices
#pragma unroll
        for (int j = 0; j < BPW; j++) {
            float2 p0 = __half22float2(a0[j]);
            float2 p1 = __half22float2(a1[j]);
            accF[j].x += p0.x; accF[j].y += p0.y;
            accF[j].z += p1.x; accF[j].w += p1.y;
        }
        __syncthreads();   // window barrier: seals preload, frees old buffer
    }

    // Coalesced packed-half2 (uint2) stores into [c][b][o] scratch.
#pragma unroll
    for (int j = 0; j < BPW; j++) {
        __half2 ph0 = __floats2half2_rn(accF[j].x, accF[j].y);
        __half2 ph1 = __floats2half2_rn(accF[j].z, accF[j].w);
        uint2 pk;
        pk.x = *(unsigned*)&ph0;
        pk.y = *(unsigned*)&ph1;
        ((uint2*)&g_partialH[chunk][b0 + wb + j][0])[lane] = pk;
    }
}

// ---------------------------------------------------------------------------
// Kernel 3 (round-10): sum the 4 fp16 partials, transpose -> out[o][b].
// ---------------------------------------------------------------------------
__global__ void reduce_kernel(float* __restrict__ out) {
    __shared__ float4 tile[32][33];
    const int b0 = blockIdx.x * 32;
    const int tx = threadIdx.x, ty = threadIdx.y;   // (32, 8)
    const size_t cstride = (size_t)B_DIM * (O_DIM / 4);   // in uint2

    const uint2* pbase = (const uint2*)&g_partialH[0][0][0];
#pragma unroll
    for (int r = 0; r < 4; r++) {
        int b = ty + r * 8;
        const uint2* p = pbase + (size_t)(b0 + b) * (O_DIM / 4) + tx;
        float4 s = make_float4(0.f, 0.f, 0.f, 0.f);
#pragma unroll
        for (int c = 0; c < C_CHUNKS; c++) {
            uint2 v = p[c * cstride];
            float2 f0 = __half22float2(*(const __half2*)&v.x);
            float2 f1 = __half22float2(*(const __half2*)&v.y);
            s.x += f0.x; s.y += f0.y; s.z += f1.x; s.w += f1.y;
        }
        tile[b][tx] = s;
    }
    __syncthreads();

    const float* tf = (const float*)tile;   // row stride = 132 floats
#pragma unroll
    for (int r = 0; r < 16; r++) {
        int o = ty + r * 8;
        out[(size_t)o * B_DIM + b0 + tx] = tf[tx * 132 + o];
    }
}

// ---------------------------------------------------------------------------
extern "C" void kernel_launch(void* const* d_in, const int* in_sizes, int n_in,
                              void* d_out, int out_size) {
    const float* x       = (const float*)d_in[0];   // [128, 8192]
    const float* P       = (const float*)d_in[1];   // [129, 128, 128]
    const float* borders = (const float*)d_in[2];   // [129]
    const float* invl    = (const float*)d_in[3];   // [128]
    float*       out     = (float*)d_out;           // [128, 8192]

    cudaFuncSetAttribute(main_kernel,
                         cudaFuncAttributeMaxDynamicSharedMemorySize, SMEM_MAIN);

    transpose_kernel<<<dim3(I_DIM / TI, 65), 256>>>(P);
    main_kernel<<<dim3(NBT, C_CHUNKS), THREADS, SMEM_MAIN>>>(x, borders, invl);
    reduce_kernel<<<B_DIM / 32, dim3(32, 8)>>>(out);
}

// round 14
// speedup vs baseline: 1.0484x; 1.0484x over previous
#include <cuda_runtime.h>
#include <cuda_fp16.h>

#define I_DIM   128
#define O_DIM   128
#define G_NUM   128
#define G1      129
#define B_DIM   8192
#define C_CHUNKS 4
#define ICHUNK  (I_DIM / C_CHUNKS)   /* 32 */
#define BT      256                  /* batch columns per block */
#define NBT     (B_DIM / BT)         /* 32 */
#define THREADS 512
#define NWARP   (THREADS / 32)       /* 16 */
#define BPW     (BT / NWARP)         /* 16 batch columns per warp */
#define ROW_U2  (O_DIM / 4)          /* 32 uint2 per 256B fp16 row */
#define GRID_BLKS (NBT * C_CHUNKS)   /* 128: all co-resident (<=148 SMs) */
#define N_UNITS  (G1 * 4)            /* 516 transpose units (g, itile) */
#define TTILE_B  (128 * 33 * 4)      /* 16896 B per warp-group tile */
#define SMEM_DYN (4 * TTILE_B)       /* 67584 B */

// Static device scratch (allocation-free per harness rules)
__device__ __align__(256) __half g_P2h[(size_t)I_DIM * G1 * O_DIM];   // [i][g][o]
__device__ __align__(16) __half g_partialH[C_CHUNKS][B_DIM][O_DIM];   // [c][b][o]
__device__ unsigned g_sync;          // global-barrier counter (monotonic)
__device__ unsigned g_red[NBT];      // per-btile completion counters (monotonic)

__device__ __forceinline__ void group_bar(int id) {
    asm volatile("bar.sync %0, 128;" :: "r"(id) : "memory");
}

// ---------------------------------------------------------------------------
// ONE fused persistent kernel: transpose -> global barrier -> gather -> reduce
// ---------------------------------------------------------------------------
__global__ __launch_bounds__(THREADS, 1)
void fused_kernel(const float* __restrict__ P,
                  const float* __restrict__ x,
                  const float* __restrict__ borders,
                  const float* __restrict__ invl,
                  float* __restrict__ out) {
    extern __shared__ __align__(16) char dyn[];
    __shared__ float s_b[G1];
    __shared__ float s_il[G_NUM];
    __shared__ int s_do;

    const int t     = threadIdx.x;
    const int btile = blockIdx.x;                 // 0..31
    const int chunk = blockIdx.y;                 // 0..3
    const int bid   = blockIdx.y * NBT + blockIdx.x;   // 0..127
    const int b0    = btile * BT;
    const int i0    = chunk * ICHUNK;

    if (t < G1)    s_b[t]  = borders[t];
    if (t < G_NUM) s_il[t] = invl[t];

    // ===== Stage 1: cooperative transpose+quantize P[g][o][i] -> P2h[i][g][o]
    // 516 units of (one g, 32 i) handled by 4 warp-groups per block, exact
    // round-4 proven body, group-scoped named barriers.
    {
        const int wgrp   = t >> 7;            // 0..3
        const int wg_tid = t & 127;
        const int ww   = wg_tid >> 5;         // 0..3 warp in group
        const int lane = wg_tid & 31;
        const int quad = lane >> 3;           // 0..3
        const int sub  = lane & 7;            // 0..7
        float (*tile)[33] = (float(*)[33])(dyn + wgrp * TTILE_B);

#pragma unroll
        for (int rep = 0; rep < 2; rep++) {
            int u = bid * 4 + wgrp + rep * 512;
            if (u < N_UNITS) {
                const int g   = u >> 2;           // 0..128
                const int i0t = (u & 3) * 32;     // 0..96
                const float4* src = (const float4*)(P + (size_t)g * O_DIM * I_DIM + i0t);
                float4 v[8];
#pragma unroll
                for (int r = 0; r < 8; r++) {
                    int o = ww * 32 + r * 4 + quad;
                    v[r] = src[(size_t)o * (I_DIM / 4) + sub];
                }
                group_bar(wgrp + 1);   // WAR: previous rep's readers done
#pragma unroll
                for (int r = 0; r < 8; r++) {
                    int o = ww * 32 + r * 4 + quad;
                    tile[o][sub * 4 + 0] = v[r].x;
                    tile[o][sub * 4 + 1] = v[r].y;
                    tile[o][sub * 4 + 2] = v[r].z;
                    tile[o][sub * 4 + 3] = v[r].w;
                }
                group_bar(wgrp + 1);
                const int op = wg_tid & 63;
                const int il = wg_tid >> 6;       // 0..1
                __half2* dst = (__half2*)g_P2h;
#pragma unroll
                for (int r = 0; r < 16; r++) {
                    int i = il + 2 * r;           // 0..31
                    dst[((size_t)(i0t + i) * G1 + g) * (O_DIM / 2) + op] =
                        __floats2half2_rn(tile[2 * op][i], tile[2 * op + 1][i]);
                }
            }
        }
    }
    __syncthreads();   // all groups done with dyn tiles; s_b/s_il visible

    // ===== Stage 2: phase-1 descriptors (independent of the table)
    unsigned* s_gd = (unsigned*)dyn;   // [ICHUNK][BT], reuses tile space
    {
        const int bl    = t & (BT - 1);
        const int ibase = t >> 8;
#pragma unroll
        for (int p = 0; p < ICHUNK / 2; p++) {
            int il = ibase + 2 * p;
            float xv = x[(size_t)(i0 + il) * B_DIM + b0 + bl];
            float e  = __expf(-fabsf(xv));
            float cdf = (xv > 0.f) ? (1.f - 0.5f * e) : (0.5f * e);
            int g = (int)(cdf * (float)G_NUM);
            g = min(max(g, 0), G_NUM - 1);
            float d = (xv - s_b[g]) * s_il[g];
            unsigned db = (unsigned)__half_as_ushort(__float2half_rn(d));
            s_gd[il * BT + bl] = (unsigned)g | (db << 16);
        }
    }

    // ===== Stage 3: GLOBAL BARRIER (all 128 blocks co-resident, 1/SM)
    if (t == 0) {
        __threadfence();   // publish this block's table writes
        unsigned old = atomicAdd(&g_sync, 1u);
        unsigned target = (old / GRID_BLKS + 1u) * GRID_BLKS;
        while (*(volatile unsigned*)&g_sync < target) { }
        __threadfence();   // acquire side
    }
    __syncthreads();

    // ===== Stage 4: gather + lerp (round-10 proven: LDG.64, BPW=16)
    const int w    = t >> 5;
    const int lane = t & 31;
    const int wb   = w * BPW;

    const __half2 one2 = __floats2half2_rn(1.f, 1.f);
    const __half2 z2   = __floats2half2_rn(0.f, 0.f);
    const uint2* __restrict__ P2v = (const uint2*)g_P2h;

    float4 accF[BPW];
#pragma unroll
    for (int j = 0; j < BPW; j++) accF[j] = make_float4(0.f, 0.f, 0.f, 0.f);

    for (int iiB = 0; iiB < ICHUNK; iiB += 4) {
        __half2 a0[BPW], a1[BPW];
#pragma unroll
        for (int j = 0; j < BPW; j++) { a0[j] = z2; a1[j] = z2; }

#pragma unroll
        for (int u = 0; u < 4; u++) {
            const int ii = iiB + u;
            const uint2* slice = P2v + (size_t)(i0 + ii) * (G1 * ROW_U2);
#pragma unroll
            for (int j = 0; j < BPW; j++) {
                unsigned v  = s_gd[ii * BT + wb + j];   // broadcast LDS
                unsigned gi = v & 0xFFu;
                unsigned dd = __byte_perm(v, v, 0x3232);
                __half2 d2  = *(__half2*)&dd;
                __half2 w2  = __hsub2(one2, d2);
                const uint2* rowp = slice + gi * ROW_U2 + lane;
                uint2 A  = __ldg(rowp);             // row g   (256B coalesced)
                uint2 Bv = __ldg(rowp + ROW_U2);    // row g+1 (adjacent)
                a0[j] = __hfma2(w2, *(__half2*)&A.x,  a0[j]);
                a0[j] = __hfma2(d2, *(__half2*)&Bv.x, a0[j]);
                a1[j] = __hfma2(w2, *(__half2*)&A.y,  a1[j]);
                a1[j] = __hfma2(d2, *(__half2*)&Bv.y, a1[j]);
            }
        }
#pragma unroll
        for (int j = 0; j < BPW; j++) {
            float2 p0 = __half22float2(a0[j]);
            float2 p1 = __half22float2(a1[j]);
            accF[j].x += p0.x; accF[j].y += p0.y;
            accF[j].z += p1.x; accF[j].w += p1.y;
        }
        if (iiB & 4) __syncthreads();
    }

    // packed-half2 partial stores
#pragma unroll
    for (int j = 0; j < BPW; j++) {
        __half2 ph0 = __floats2half2_rn(accF[j].x, accF[j].y);
        __half2 ph1 = __floats2half2_rn(accF[j].z, accF[j].w);
        uint2 pk;
        pk.x = *(unsigned*)&ph0;
        pk.y = *(unsigned*)&ph1;
        ((uint2*)&g_partialH[chunk][b0 + wb + j][0])[lane] = pk;
    }

    // ===== Stage 5: per-btile election; last of 4 chunk-blocks reduces
    __syncthreads();   // all partial stores issued
    if (t == 0) {
        __threadfence();
        unsigned old = atomicAdd(&g_red[btile], 1u);
        s_do = ((old & 3u) == 3u);
    }
    __syncthreads();
    if (!s_do) return;

    __threadfence();   // acquire: other blocks' partials
    {
        float4* rtile = (float4*)(dyn + (t >> 8) * (32 * 33 * 16));  // 2 bufs
        const int tt = t & 255;
        const int tx = tt & 31, ty = tt >> 5;        // ty 0..7
        const int half = t >> 8;                     // 0..1
        const size_t cstride = (size_t)B_DIM * (O_DIM / 4);   // in uint2
        const uint2* pbase = (const uint2*)&g_partialH[0][0][0];

        for (int st = 0; st < 8; st += 2) {
            const int b0r = btile * BT + (st + half) * 32;
#pragma unroll
            for (int r = 0; r < 4; r++) {
                int b = ty + r * 8;
                const uint2* p = pbase + (size_t)(b0r + b) * (O_DIM / 4) + tx;
                float4 s = make_float4(0.f, 0.f, 0.f, 0.f);
#pragma unroll
                for (int c = 0; c < C_CHUNKS; c++) {
                    uint2 v = p[c * cstride];
                    float2 f0 = __half22float2(*(const __half2*)&v.x);
                    float2 f1 = __half22float2(*(const __half2*)&v.y);
                    s.x += f0.x; s.y += f0.y; s.z += f1.x; s.w += f1.y;
                }
                rtile[b * 33 + tx] = s;
            }
            __syncthreads();
            const float* tf = (const float*)rtile;   // row stride 132 floats
#pragma unroll
            for (int r = 0; r < 16; r++) {
                int o = ty + r * 8;
                out[(size_t)o * B_DIM + b0r + tx] = tf[tx * 132 + o];
            }
            __syncthreads();
        }
    }
}

// ---------------------------------------------------------------------------
extern "C" void kernel_launch(void* const* d_in, const int* in_sizes, int n_in,
                              void* d_out, int out_size) {
    const float* x       = (const float*)d_in[0];   // [128, 8192]
    const float* P       = (const float*)d_in[1];   // [129, 128, 128]
    const float* borders = (const float*)d_in[2];   // [129]
    const float* invl    = (const float*)d_in[3];   // [128]
    float*       out     = (float*)d_out;           // [128, 8192]

    cudaFuncSetAttribute(fused_kernel,
                         cudaFuncAttributeMaxDynamicSharedMemorySize, SMEM_DYN);
    fused_kernel<<<dim3(NBT, C_CHUNKS), THREADS, SMEM_DYN>>>(P, x, borders, invl, out);
}

// round 15
// speedup vs baseline: 1.2556x; 1.1977x over previous
#include <cuda_runtime.h>
#include <cuda_fp16.h>

#define I_DIM   128
#define O_DIM   128
#define G_NUM   128
#define G1      129
#define B_DIM   8192
#define C_CHUNKS 4
#define ICHUNK  (I_DIM / C_CHUNKS)   /* 32 */
#define BT      256                  /* batch columns per block */
#define NBT     (B_DIM / BT)         /* 32 */
#define THREADS 512
#define NWARP   (THREADS / 32)       /* 16 */
#define BPW     (BT / NWARP)         /* 16 batch columns per warp */
#define TI      16                   /* i per transpose tile */

#define SLB2    (G1 * 256)           /* 33024 B: one full fp16 slice */
#define SLB_U4  (SLB2 / 16)          /* 2064 cp.async units */

// dynamic smem layout (main kernel)
#define OFF_RING  0                          /* 4 x 33024 = 132096 */
#define OFF_GD    (4 * SLB2)                 /* 32768 descriptors */
#define OFF_SB    (OFF_GD + ICHUNK * BT * 4) /* 164864 */
#define OFF_SIL   (OFF_SB + 132 * 4)         /* 165392 */
#define SMEM_MAIN (OFF_SIL + 128 * 4 + 32)   /* 165936 < 227KB */

// Static device scratch (allocation-free per harness rules)
__device__ __align__(256) __half g_P2h[(size_t)I_DIM * G1 * O_DIM];   // [i][g][o]
__device__ __align__(16) __half g_partialH[C_CHUNKS][B_DIM][O_DIM];   // [c][b][o]

// ---------------------------------------------------------------------------
__device__ __forceinline__ void cp16(unsigned dst_smem, const void* src) {
    asm volatile("cp.async.cg.shared.global [%0], [%1], 16;"
                 :: "r"(dst_smem), "l"(src) : "memory");
}
__device__ __forceinline__ void cp_commit() {
    asm volatile("cp.async.commit_group;" ::: "memory");
}
template <int N>
__device__ __forceinline__ void cp_wait() {
    asm volatile("cp.async.wait_group %0;" :: "n"(N) : "memory");
}

// ---------------------------------------------------------------------------
// Kernel 1 (round-10, stable): transpose+quantize P[g][o][i] -> P2h[i][g][o].
// ---------------------------------------------------------------------------
__global__ __launch_bounds__(256, 8)
void transpose_kernel(const float* __restrict__ P) {
    __shared__ float tile[2][O_DIM][17];
    const int g0 = blockIdx.y * 2;
    const int i0 = blockIdx.x * TI;
    const int t = threadIdx.x;
    const int w = t >> 5, lane = t & 31;
    const int gg = w >> 2;
    const int w2 = w & 3;
    const int oq = lane >> 2;
    const int f4 = lane & 3;
    const int g = g0 + gg;

    if (g <= G_NUM) {
        const float4* src = (const float4*)(P + (size_t)g * O_DIM * I_DIM + i0);
        float4 v[4];
#pragma unroll
        for (int r = 0; r < 4; r++) {
            int o = w2 * 32 + r * 8 + oq;
            v[r] = src[(size_t)o * (I_DIM / 4) + f4];
        }
#pragma unroll
        for (int r = 0; r < 4; r++) {
            int o = w2 * 32 + r * 8 + oq;
            tile[gg][o][f4 * 4 + 0] = v[r].x;
            tile[gg][o][f4 * 4 + 1] = v[r].y;
            tile[gg][o][f4 * 4 + 2] = v[r].z;
            tile[gg][o][f4 * 4 + 3] = v[r].w;
        }
    }
    __syncthreads();

    const int op  = t & 63;
    const int il  = (t >> 6) & 1;
    const int gg2 = t >> 7;
    const int gs  = g0 + gg2;
    if (gs <= G_NUM) {
        __half2* dst = (__half2*)g_P2h;
#pragma unroll
        for (int r = 0; r < 8; r++) {
            int i = il + 2 * r;
            dst[((size_t)(i0 + i) * G1 + gs) * (O_DIM / 2) + op] =
                __floats2half2_rn(tile[gg2][2 * op][i], tile[gg2][2 * op + 1][i]);
        }
    }
}

// ---------------------------------------------------------------------------
// Kernel 2: smem-routed gather. Each slice (33KB) is staged into a 4-deep
// ring via cp.async.cg (bypasses L1); ALL gathers are conflict-free LDS.128
// through the crossbar. Lanes 0-15 serve one column of a pair, 16-31 the
// other: lane covers 8 outputs (uint4).
// ---------------------------------------------------------------------------
__global__ __launch_bounds__(THREADS, 1)
void main_kernel(const float* __restrict__ x,
                 const float* __restrict__ borders,
                 const float* __restrict__ invl) {
    extern __shared__ __align__(16) char dyn[];
    unsigned* s_gd = (unsigned*)(dyn + OFF_GD);   // [ICHUNK][BT]
    float*    s_b  = (float*)(dyn + OFF_SB);
    float*    s_il = (float*)(dyn + OFF_SIL);
    const unsigned ringS = (unsigned)__cvta_generic_to_shared(dyn + OFF_RING);

    const int t     = threadIdx.x;
    const int btile = blockIdx.x;    // 0..31
    const int chunk = blockIdx.y;    // 0..3
    const int b0    = btile * BT;
    const int i0    = chunk * ICHUNK;

    if (t < G1)    s_b[t]  = borders[t];
    if (t < G_NUM) s_il[t] = invl[t];

    // Prologue: stage slices i0..i0+2 into ring bufs 0..2 (flies over phase 1)
    const char* gbase = (const char*)g_P2h + (size_t)i0 * SLB2;
#pragma unroll
    for (int s = 0; s < 3; s++) {
        for (int k = t; k < SLB_U4; k += THREADS)
            cp16(ringS + s * SLB2 + k * 16, gbase + (size_t)s * SLB2 + k * 16);
        cp_commit();
    }
    __syncthreads();   // s_b/s_il visible

    // Phase 1: bucket index g + weight d, packed (g | half(d)<<16)
    {
        const int bl    = t & (BT - 1);
        const int ibase = t >> 8;
#pragma unroll
        for (int p = 0; p < ICHUNK / 2; p++) {
            int il = ibase + 2 * p;
            float xv = x[(size_t)(i0 + il) * B_DIM + b0 + bl];
            float e  = __expf(-fabsf(xv));
            float cdf = (xv > 0.f) ? (1.f - 0.5f * e) : (0.5f * e);
            int g = (int)(cdf * (float)G_NUM);
            g = min(max(g, 0), G_NUM - 1);
            float d = (xv - s_b[g]) * s_il[g];
            unsigned db = (unsigned)__half_as_ushort(__float2half_rn(d));
            s_gd[il * BT + bl] = (unsigned)g | (db << 16);
        }
    }
    __syncthreads();

    const int w    = t >> 5;
    const int lane = t & 31;
    const int wb   = w * BPW;        // 16 cols per warp
    const int h    = lane >> 4;      // 0..1: column within pair
    const int le   = lane & 15;      // 16B chunk (8 outputs) of 256B row

    const __half2 one2 = __floats2half2_rn(1.f, 1.f);
    const __half2 z2   = __floats2half2_rn(0.f, 0.f);

    float4 accF[8][2];               // 8 col-pairs x 8 outputs fp32
#pragma unroll
    for (int jj = 0; jj < 8; jj++) {
        accF[jj][0] = make_float4(0.f, 0.f, 0.f, 0.f);
        accF[jj][1] = make_float4(0.f, 0.f, 0.f, 0.f);
    }

    for (int W = 0; W < ICHUNK / 4; W++) {
        __half2 hac[8][4];
#pragma unroll
        for (int jj = 0; jj < 8; jj++) {
            hac[jj][0] = z2; hac[jj][1] = z2; hac[jj][2] = z2; hac[jj][3] = z2;
        }

#pragma unroll
        for (int u = 0; u < 4; u++) {
            const int ii = W * 4 + u;
            cp_wait<2>();      // slice ii resident in buf[ii&3]
            __syncthreads();   // all warps past slice ii-1 -> its buf is free

            if (ii + 3 < ICHUNK) {
                const char* src = gbase + (size_t)(ii + 3) * SLB2;
                unsigned dst = ringS + ((ii + 3) & 3) * SLB2;
                for (int k = t; k < SLB_U4; k += THREADS)
                    cp16(dst + k * 16, src + k * 16);
            }
            cp_commit();   // unconditional: uniform group bookkeeping

            const char* sbuf = dyn + OFF_RING + (ii & 3) * SLB2;
#pragma unroll
            for (int jj = 0; jj < 8; jj++) {
                unsigned v  = s_gd[ii * BT + wb + 2 * jj + h];  // 2-way bcast
                unsigned gi = v & 0xFFu;
                unsigned dd = __byte_perm(v, v, 0x3232);
                __half2 d2  = *(__half2*)&dd;
                __half2 w2  = __hsub2(one2, d2);
                const uint4* pa = (const uint4*)(sbuf + gi * 256) + le;
                uint4 A  = pa[0];     // row g   (LDS.128, conflict-free)
                uint4 Bv = pa[16];    // row g+1 (+256B)
                hac[jj][0] = __hfma2(d2, *(__half2*)&Bv.x, __hfma2(w2, *(__half2*)&A.x, hac[jj][0]));
                hac[jj][1] = __hfma2(d2, *(__half2*)&Bv.y, __hfma2(w2, *(__half2*)&A.y, hac[jj][1]));
                hac[jj][2] = __hfma2(d2, *(__half2*)&Bv.z, __hfma2(w2, *(__half2*)&A.z, hac[jj][2]));
                hac[jj][3] = __hfma2(d2, *(__half2*)&Bv.w, __hfma2(w2, *(__half2*)&A.w, hac[jj][3]));
            }
        }

        // flush half2 partials into fp32 accumulators every 4 slices
#pragma unroll
        for (int jj = 0; jj < 8; jj++) {
            float2 p0 = __half22float2(hac[jj][0]);
            float2 p1 = __half22float2(hac[jj][1]);
            float2 p2 = __half22float2(hac[jj][2]);
            float2 p3 = __half22float2(hac[jj][3]);
            accF[jj][0].x += p0.x; accF[jj][0].y += p0.y;
            accF[jj][0].z += p1.x; accF[jj][0].w += p1.y;
            accF[jj][1].x += p2.x; accF[jj][1].y += p2.y;
            accF[jj][1].z += p3.x; accF[jj][1].w += p3.y;
        }
    }

    // Store: lane's column = wb + 2jj + h, outputs [8le, 8le+8) -> uint4.
#pragma unroll
    for (int jj = 0; jj < 8; jj++) {
        __half2 q0 = __floats2half2_rn(accF[jj][0].x, accF[jj][0].y);
        __half2 q1 = __floats2half2_rn(accF[jj][0].z, accF[jj][0].w);
        __half2 q2 = __floats2half2_rn(accF[jj][1].x, accF[jj][1].y);
        __half2 q3 = __floats2half2_rn(accF[jj][1].z, accF[jj][1].w);
        uint4 pk;
        pk.x = *(unsigned*)&q0; pk.y = *(unsigned*)&q1;
        pk.z = *(unsigned*)&q2; pk.w = *(unsigned*)&q3;
        int b = b0 + wb + 2 * jj + h;
        *(uint4*)&g_partialH[chunk][b][le * 8] = pk;
    }
}

// ---------------------------------------------------------------------------
// Kernel 3 (round-10): sum the 4 fp16 partials, transpose -> out[o][b].
// ---------------------------------------------------------------------------
__global__ void reduce_kernel(float* __restrict__ out) {
    __shared__ float4 tile[32][33];
    const int b0 = blockIdx.x * 32;
    const int tx = threadIdx.x, ty = threadIdx.y;   // (32, 8)
    const size_t cstride = (size_t)B_DIM * (O_DIM / 4);   // in uint2

    const uint2* pbase = (const uint2*)&g_partialH[0][0][0];
#pragma unroll
    for (int r = 0; r < 4; r++) {
        int b = ty + r * 8;
        const uint2* p = pbase + (size_t)(b0 + b) * (O_DIM / 4) + tx;
        float4 s = make_float4(0.f, 0.f, 0.f, 0.f);
#pragma unroll
        for (int c = 0; c < C_CHUNKS; c++) {
            uint2 v = p[c * cstride];
            float2 f0 = __half22float2(*(const __half2*)&v.x);
            float2 f1 = __half22float2(*(const __half2*)&v.y);
            s.x += f0.x; s.y += f0.y; s.z += f1.x; s.w += f1.y;
        }
        tile[b][tx] = s;
    }
    __syncthreads();

    const float* tf = (const float*)tile;   // row stride = 132 floats
#pragma unroll
    for (int r = 0; r < 16; r++) {
        int o = ty + r * 8;
        out[(size_t)o * B_DIM + b0 + tx] = tf[tx * 132 + o];
    }
}

// ---------------------------------------------------------------------------
extern "C" void kernel_launch(void* const* d_in, const int* in_sizes, int n_in,
                              void* d_out, int out_size) {
    const float* x       = (const float*)d_in[0];   // [128, 8192]
    const float* P       = (const float*)d_in[1];   // [129, 128, 128]
    const float* borders = (const float*)d_in[2];   // [129]
    const float* invl    = (const float*)d_in[3];   // [128]
    float*       out     = (float*)d_out;           // [128, 8192]

    cudaFuncSetAttribute(main_kernel,
                         cudaFuncAttributeMaxDynamicSharedMemorySize, SMEM_MAIN);

    transpose_kernel<<<dim3(I_DIM / TI, 65), 256>>>(P);
    main_kernel<<<dim3(NBT, C_CHUNKS), THREADS, SMEM_MAIN>>>(x, borders, invl);
    reduce_kernel<<<B_DIM / 32, dim3(32, 8)>>>(out);
}